// round 1
// baseline (speedup 1.0000x reference)
#include <cuda_runtime.h>
#include <math.h>

#define NN 4096
#define FIN 3000
#define FOUT 64
#define MAXNNZ 512
#define KSPLIT 8

// ---------------- scratch (static device memory; no allocation) ----------------
__device__ float g_X1 [NN*FOUT];
__device__ float g_X1a[NN*FOUT];
__device__ float g_Wh [NN*FOUT];
__device__ float g_s  [NN];
__device__ float g_d  [NN];
__device__ float g_att[NN*FOUT];
__device__ float g_t1 [NN*256];
__device__ float g_t2 [NN*128];
__device__ float g_z  [NN*FOUT];
__device__ float g_za [NN*FOUT];
__device__ float g_zw2[NN*FIN];
__device__ float g_emb [NN*FOUT];
__device__ float g_emba[NN*FOUT];
__device__ float g_g  [NN*FOUT];
__device__ float g_ga [NN*FOUT];
__device__ float g_dc [NN*FOUT];
__device__ float g_dca[NN*FOUT];
__device__ float g_dpl[NN*FOUT];
__device__ float g_dmi[NN*FOUT];
__device__ float g_u  [NN*FOUT];
__device__ float g_ua [NN*FOUT];
__device__ float g_dh [NN*128];
__device__ float g_part[KSPLIT*NN*FOUT];
__device__ float g_WT [FOUT*FOUT];
__device__ int   g_adj_idx[NN*MAXNNZ];
__device__ int   g_adj_cnt[NN];
__device__ int   g_gn_idx [NN*MAXNNZ];
__device__ int   g_gn_cnt [NN];

// ---------------- build sparse row lists (deterministic order) ----------------
__global__ void build_list_kernel(const float* __restrict__ mat, int* __restrict__ idx,
                                  int* __restrict__ cnt) {
    int row = blockIdx.x;
    int tid = threadIdx.x;
    const float* r = mat + (size_t)row * NN;
    __shared__ int counts[256];
    __shared__ int offs[256];
    int base = tid * 16;
    int c = 0;
    #pragma unroll
    for (int j = 0; j < 16; j++) c += (r[base + j] != 0.0f);
    counts[tid] = c;
    __syncthreads();
    if (tid == 0) {
        int acc = 0;
        for (int i = 0; i < 256; i++) { offs[i] = acc; acc += counts[i]; }
        cnt[row] = acc;
    }
    __syncthreads();
    int o = offs[tid];
    int* dst = idx + (size_t)row * MAXNNZ;
    #pragma unroll
    for (int j = 0; j < 16; j++) {
        if (r[base + j] != 0.0f) dst[o++] = base + j;
    }
}

// ---------------- generic tiled fp32 GEMM: C = act(A@B + bias) ----------------
// BM=64, BN=64, BK=16, 256 threads, 4x4 per thread. split-K via blockIdx.z.
__global__ void gemm_kernel(const float* __restrict__ A, const float* __restrict__ B,
                            const float* __restrict__ bias, float* __restrict__ C,
                            int M, int N, int K, int kChunk, long long partStride, int act) {
    int bz = blockIdx.z;
    int k0 = bz * kChunk;
    int k1 = min(K, k0 + kChunk);
    float* Cp = C + (long long)bz * partStride;
    int row0 = blockIdx.y * 64;
    int col0 = blockIdx.x * 64;
    int tid = threadIdx.x;
    int tx = tid & 15, ty = tid >> 4;

    __shared__ float As[16][64];
    __shared__ float Bs[16][65];

    float acc[4][4];
    #pragma unroll
    for (int i = 0; i < 4; i++)
        #pragma unroll
        for (int j = 0; j < 4; j++) acc[i][j] = 0.0f;

    for (int kk = k0; kk < k1; kk += 16) {
        #pragma unroll
        for (int t = tid; t < 1024; t += 256) {
            int m = t >> 4, k = t & 15;
            int gk = kk + k;
            As[k][m] = (gk < k1) ? A[(size_t)(row0 + m) * K + gk] : 0.0f;
        }
        #pragma unroll
        for (int t = tid; t < 1024; t += 256) {
            int k = t >> 6, n = t & 63;
            int gk = kk + k, gn = col0 + n;
            Bs[k][n] = (gk < k1 && gn < N) ? B[(size_t)gk * N + gn] : 0.0f;
        }
        __syncthreads();
        #pragma unroll
        for (int k = 0; k < 16; k++) {
            float a0 = As[k][ty * 4 + 0], a1 = As[k][ty * 4 + 1];
            float a2 = As[k][ty * 4 + 2], a3 = As[k][ty * 4 + 3];
            float b0 = Bs[k][tx * 4 + 0], b1 = Bs[k][tx * 4 + 1];
            float b2 = Bs[k][tx * 4 + 2], b3 = Bs[k][tx * 4 + 3];
            acc[0][0] += a0 * b0; acc[0][1] += a0 * b1; acc[0][2] += a0 * b2; acc[0][3] += a0 * b3;
            acc[1][0] += a1 * b0; acc[1][1] += a1 * b1; acc[1][2] += a1 * b2; acc[1][3] += a1 * b3;
            acc[2][0] += a2 * b0; acc[2][1] += a2 * b1; acc[2][2] += a2 * b2; acc[2][3] += a2 * b3;
            acc[3][0] += a3 * b0; acc[3][1] += a3 * b1; acc[3][2] += a3 * b2; acc[3][3] += a3 * b3;
        }
        __syncthreads();
    }
    #pragma unroll
    for (int i = 0; i < 4; i++) {
        int r = row0 + ty * 4 + i;
        #pragma unroll
        for (int j = 0; j < 4; j++) {
            int c = col0 + tx * 4 + j;
            if (c < N) {
                float v = acc[i][j];
                if (bias) v += bias[c];
                if (act) v = fmaxf(v, 0.0f);
                Cp[(size_t)r * N + c] = v;
            }
        }
    }
}

__global__ void reduce_part_kernel(const float* __restrict__ part, float* __restrict__ out,
                                   int mn, int parts) {
    int i = blockIdx.x * blockDim.x + threadIdx.x;
    if (i < mn) {
        float s = 0.0f;
        for (int z = 0; z < parts; z++) s += part[(size_t)z * mn + i];
        out[i] = s;
    }
}

// ---------------- s = Wh@a_src, d = Wh@a_dst (warp per row) ----------------
__global__ void sd_kernel(const float* __restrict__ Wh, const float* __restrict__ a_src,
                          const float* __restrict__ a_dst, float* __restrict__ s,
                          float* __restrict__ d) {
    int row = blockIdx.x * 8 + (threadIdx.x >> 5);
    int lane = threadIdx.x & 31;
    if (row < NN) {
        const float* w = Wh + (size_t)row * 64;
        float vs = w[lane] * a_src[lane] + w[lane + 32] * a_src[lane + 32];
        float vd = w[lane] * a_dst[lane] + w[lane + 32] * a_dst[lane + 32];
        #pragma unroll
        for (int o = 16; o > 0; o >>= 1) {
            vs += __shfl_down_sync(0xffffffffu, vs, o);
            vd += __shfl_down_sync(0xffffffffu, vd, o);
        }
        if (lane == 0) { s[row] = vs; d[row] = vd; }
    }
}

// ---------------- sparse masked softmax + spmm with Wh ----------------
__global__ void att_kernel(const int* __restrict__ idx, const int* __restrict__ cnt,
                           const float* __restrict__ s, const float* __restrict__ d,
                           const float* __restrict__ Wh, float* __restrict__ out) {
    int row = blockIdx.x, tid = threadIdx.x;
    int n = cnt[row];
    const int* lst = idx + (size_t)row * MAXNNZ;
    __shared__ float e[MAXNNZ];
    __shared__ float red[256];
    __shared__ float accsh[4][64];
    float si = s[row];
    float mx = -3.4e38f;
    for (int t = tid; t < n; t += 256) {
        int j = lst[t];
        float v = si + d[j];
        v = v > 0.0f ? v : 0.2f * v;   // LeakyReLU(0.2)
        e[t] = v;
        mx = fmaxf(mx, v);
    }
    red[tid] = mx;
    __syncthreads();
    for (int st = 128; st > 0; st >>= 1) {
        if (tid < st) red[tid] = fmaxf(red[tid], red[tid + st]);
        __syncthreads();
    }
    mx = red[0];
    __syncthreads();
    float sm = 0.0f;
    for (int t = tid; t < n; t += 256) {
        float w = expf(e[t] - mx);
        e[t] = w;
        sm += w;
    }
    red[tid] = sm;
    __syncthreads();
    for (int st = 128; st > 0; st >>= 1) {
        if (tid < st) red[tid] += red[tid + st];
        __syncthreads();
    }
    float inv = 1.0f / red[0];
    int grp = tid >> 6, lane = tid & 63;
    float acc = 0.0f;
    for (int t = grp; t < n; t += 4) acc += e[t] * Wh[(size_t)lst[t] * 64 + lane];
    accsh[grp][lane] = acc;
    __syncthreads();
    if (grp == 0)
        out[(size_t)row * 64 + lane] =
            (accsh[0][lane] + accsh[1][lane] + accsh[2][lane] + accsh[3][lane]) * inv;
}

// ---------------- h = adj-spmm over wide matrix (3000 cols) ----------------
__global__ void spmm_wide_kernel(const int* __restrict__ idx, const int* __restrict__ cnt,
                                 const float* __restrict__ Mm, float* __restrict__ out) {
    int row = blockIdx.x, tid = threadIdx.x;
    int n = cnt[row];
    __shared__ int lst[MAXNNZ];
    for (int t = tid; t < n; t += 256) lst[t] = idx[(size_t)row * MAXNNZ + t];
    __syncthreads();
    for (int c = tid; c < FIN; c += 256) {
        float a = 0.0f;
        for (int t = 0; t < n; t++) a += Mm[(size_t)lst[t] * FIN + c];
        out[(size_t)row * FIN + c] = a;
    }
}

// ---------------- readout: mean over gn-list, L2 normalize, sigmoid ----------------
__global__ void readout_kernel(const int* __restrict__ idx, const int* __restrict__ cnt,
                               const float* __restrict__ emb, float* __restrict__ g) {
    int row = blockIdx.x, tid = threadIdx.x;
    int n = cnt[row];
    const int* lst = idx + (size_t)row * MAXNNZ;
    __shared__ float accsh[4][64];
    __shared__ float v[64];
    __shared__ float red[64];
    int grp = tid >> 6, lane = tid & 63;
    float a = 0.0f;
    for (int t = grp; t < n; t += 4) a += emb[(size_t)lst[t] * 64 + lane];
    accsh[grp][lane] = a;
    __syncthreads();
    if (grp == 0)
        v[lane] = (accsh[0][lane] + accsh[1][lane] + accsh[2][lane] + accsh[3][lane]) / (float)n;
    __syncthreads();
    if (tid < 64) red[tid] = v[tid] * v[tid];
    __syncthreads();
    for (int st = 32; st > 0; st >>= 1) {
        if (tid < st) red[tid] += red[tid + st];
        __syncthreads();
    }
    float den = fmaxf(sqrtf(red[0]), 1e-12f);
    if (tid < 64) {
        float x = v[tid] / den;
        g[(size_t)row * 64 + tid] = 1.0f / (1.0f + expf(-x));
    }
}

// ---------------- elementwise ----------------
__global__ void relu_kernel(const float* __restrict__ in, float* __restrict__ out, int n) {
    int i = blockIdx.x * blockDim.x + threadIdx.x;
    if (i < n) out[i] = fmaxf(in[i], 0.0f);
}
__global__ void copy_kernel(const float* __restrict__ in, float* __restrict__ out, int n) {
    int i = blockIdx.x * blockDim.x + threadIdx.x;
    if (i < n) out[i] = in[i];
}
__global__ void transpose64_kernel(const float* __restrict__ W, float* __restrict__ WT) {
    for (int t = threadIdx.x; t < 64 * 64; t += blockDim.x) {
        int i = t >> 6, j = t & 63;
        WT[j * 64 + i] = W[t];
    }
}

// ---------------- bilinear outputs: out[:,0]=rowdot(x0,u)+b, out[:,1]=rowdot(x1,u)+b --------
__global__ void bilin_kernel(const float* __restrict__ x0, const float* __restrict__ x1,
                             const float* __restrict__ u, const float* __restrict__ b,
                             float* __restrict__ out) {
    int row = blockIdx.x * 8 + (threadIdx.x >> 5);
    int lane = threadIdx.x & 31;
    if (row < NN) {
        const float* ur = u + (size_t)row * 64;
        const float* r0 = x0 + (size_t)row * 64;
        const float* r1 = x1 + (size_t)row * 64;
        float v0 = r0[lane] * ur[lane] + r0[lane + 32] * ur[lane + 32];
        float v1 = r1[lane] * ur[lane] + r1[lane + 32] * ur[lane + 32];
        #pragma unroll
        for (int o = 16; o > 0; o >>= 1) {
            v0 += __shfl_down_sync(0xffffffffu, v0, o);
            v1 += __shfl_down_sync(0xffffffffu, v1, o);
        }
        if (lane == 0) {
            out[(size_t)row * 2 + 0] = v0 + b[0];
            out[(size_t)row * 2 + 1] = v1 + b[0];
        }
    }
}

// ---------------- host ----------------
static void* sym(const void* s) {
    void* p = nullptr;
    cudaGetSymbolAddress(&p, s);
    return p;
}

extern "C" void kernel_launch(void* const* d_in, const int* in_sizes, int n_in,
                              void* d_out, int out_size) {
    const float* feat   = (const float*)d_in[0];
    const float* feat_a = (const float*)d_in[1];
    const float* adj    = (const float*)d_in[2];
    const float* gn     = (const float*)d_in[3];
    const float* w1     = (const float*)d_in[4];
    const float* w2     = (const float*)d_in[5];
    const float* attW   = (const float*)d_in[6];
    const float* a_src  = (const float*)d_in[7];
    const float* a_dst  = (const float*)d_in[8];
    const float* mW1 = (const float*)d_in[9];  const float* mb1 = (const float*)d_in[10];
    const float* mW2 = (const float*)d_in[11]; const float* mb2 = (const float*)d_in[12];
    const float* mW3 = (const float*)d_in[13]; const float* mb3 = (const float*)d_in[14];
    const float* dW1 = (const float*)d_in[15]; const float* db1 = (const float*)d_in[16];
    const float* dW2 = (const float*)d_in[17]; const float* db2 = (const float*)d_in[18];
    const float* bilW = (const float*)d_in[19];
    const float* bilb = (const float*)d_in[20];

    float* out      = (float*)d_out;
    float* out_h    = out + (size_t)NN * FOUT;
    float* out_ret  = out_h + (size_t)NN * FIN;
    float* out_reta = out_ret + (size_t)NN * 2;

    float* X1  = (float*)sym(g_X1);   float* X1a = (float*)sym(g_X1a);
    float* Wh  = (float*)sym(g_Wh);
    float* sv  = (float*)sym(g_s);    float* dv  = (float*)sym(g_d);
    float* att = (float*)sym(g_att);
    float* t1  = (float*)sym(g_t1);   float* t2  = (float*)sym(g_t2);
    float* z   = (float*)sym(g_z);    float* za  = (float*)sym(g_za);
    float* zw2 = (float*)sym(g_zw2);
    float* emb = (float*)sym(g_emb);  float* emba = (float*)sym(g_emba);
    float* gv  = (float*)sym(g_g);    float* gva  = (float*)sym(g_ga);
    float* dc  = (float*)sym(g_dc);   float* dca  = (float*)sym(g_dca);
    float* dpl = (float*)sym(g_dpl);  float* dmi  = (float*)sym(g_dmi);
    float* u   = (float*)sym(g_u);    float* ua   = (float*)sym(g_ua);
    float* dh  = (float*)sym(g_dh);
    float* part = (float*)sym(g_part);
    float* WT  = (float*)sym(g_WT);
    int* aidx = (int*)sym(g_adj_idx); int* acnt = (int*)sym(g_adj_cnt);
    int* gidx = (int*)sym(g_gn_idx);  int* gcnt = (int*)sym(g_gn_cnt);

    // 1. sparse lists (adj read once, gn read once)
    build_list_kernel<<<NN, 256>>>(adj, aidx, acnt);
    build_list_kernel<<<NN, 256>>>(gn, gidx, gcnt);

    // 2. X1 = feat @ w1, X1a = feat_a @ w1   (split-K=8, K chunk 375)
    {
        dim3 grid(1, NN / 64, KSPLIT);
        long long ps = (long long)NN * FOUT;
        gemm_kernel<<<grid, 256>>>(feat, w1, nullptr, part, NN, FOUT, FIN, 375, ps, 0);
        reduce_part_kernel<<<(NN * FOUT + 255) / 256, 256>>>(part, X1, NN * FOUT, KSPLIT);
        gemm_kernel<<<grid, 256>>>(feat_a, w1, nullptr, part, NN, FOUT, FIN, 375, ps, 0);
        reduce_part_kernel<<<(NN * FOUT + 255) / 256, 256>>>(part, X1a, NN * FOUT, KSPLIT);
    }

    // 3. two GAT+MLP paths
    for (int p = 0; p < 2; p++) {
        const float* X = p == 0 ? X1 : X1a;
        float* zz = p == 0 ? z : za;
        gemm_kernel<<<dim3(1, NN / 64, 1), 256>>>(X, attW, nullptr, Wh, NN, 64, 64, 64, 0, 0);
        sd_kernel<<<NN / 8, 256>>>(Wh, a_src, a_dst, sv, dv);
        att_kernel<<<NN, 256>>>(aidx, acnt, sv, dv, Wh, att);
        gemm_kernel<<<dim3(4, NN / 64, 1), 256>>>(att, mW1, mb1, t1, NN, 256, 64, 64, 0, 1);
        gemm_kernel<<<dim3(2, NN / 64, 1), 256>>>(t1, mW2, mb2, t2, NN, 128, 256, 256, 0, 1);
        gemm_kernel<<<dim3(1, NN / 64, 1), 256>>>(t2, mW3, mb3, zz, NN, 64, 128, 128, 0, 0);
    }

    // 4. hiden_emb = z
    copy_kernel<<<(NN * FOUT + 255) / 256, 256>>>(z, out, NN * FOUT);

    // 5. h = adj @ (z @ w2)
    gemm_kernel<<<dim3((FIN + 63) / 64, NN / 64, 1), 256>>>(z, w2, nullptr, zw2, NN, FIN, 64, 64, 0, 0);
    spmm_wide_kernel<<<NN, 256>>>(aidx, acnt, zw2, out_h);

    // 6. emb / emb_a, readouts
    relu_kernel<<<(NN * FOUT + 255) / 256, 256>>>(z, emb, NN * FOUT);
    relu_kernel<<<(NN * FOUT + 255) / 256, 256>>>(za, emba, NN * FOUT);
    readout_kernel<<<NN, 256>>>(gidx, gcnt, emb, gv);
    readout_kernel<<<NN, 256>>>(gidx, gcnt, emba, gva);

    // 7. discriminator MLPs
    const float* dins[4] = { gv, gva, emb, emba };
    float* douts[4] = { dc, dca, dpl, dmi };
    for (int i = 0; i < 4; i++) {
        gemm_kernel<<<dim3(2, NN / 64, 1), 256>>>(dins[i], dW1, db1, dh, NN, 128, 64, 64, 0, 1);
        gemm_kernel<<<dim3(1, NN / 64, 1), 256>>>(dh, dW2, db2, douts[i], NN, 64, 128, 128, 0, 0);
    }

    // 8. bilinear: u = dc @ bilW^T ; ret[:,0]=dot(dpl,u)+b, ret[:,1]=dot(dmi,u)+b
    transpose64_kernel<<<1, 256>>>(bilW, WT);
    gemm_kernel<<<dim3(1, NN / 64, 1), 256>>>(dc, WT, nullptr, u, NN, 64, 64, 64, 0, 0);
    gemm_kernel<<<dim3(1, NN / 64, 1), 256>>>(dca, WT, nullptr, ua, NN, 64, 64, 64, 0, 0);
    bilin_kernel<<<NN / 8, 256>>>(dpl, dmi, u, bilb, out_ret);
    bilin_kernel<<<NN / 8, 256>>>(dmi, dpl, ua, bilb, out_reta);
}

// round 3
// speedup vs baseline: 1.3382x; 1.3382x over previous
#include <cuda_runtime.h>
#include <math.h>
#include <mma.h>

using namespace nvcuda;

#define NN 4096
#define FIN 3000
#define FOUT 64
#define MAXNNZ 512
#define KSPLIT 8

// ---------------- scratch (static device memory; no allocation) ----------------
__device__ float g_X1 [NN*FOUT];
__device__ float g_X1a[NN*FOUT];
__device__ float g_Wh [NN*FOUT];
__device__ float g_s  [NN];
__device__ float g_d  [NN];
__device__ float g_att[NN*FOUT];
__device__ float g_t1 [NN*256];
__device__ float g_t2 [NN*128];
__device__ float g_z  [NN*FOUT];
__device__ float g_za [NN*FOUT];
__device__ float g_adjz[NN*FOUT];
__device__ float g_emb [NN*FOUT];
__device__ float g_emba[NN*FOUT];
__device__ float g_g  [NN*FOUT];
__device__ float g_ga [NN*FOUT];
__device__ float g_dc [NN*FOUT];
__device__ float g_dca[NN*FOUT];
__device__ float g_dpl[NN*FOUT];
__device__ float g_dmi[NN*FOUT];
__device__ float g_u  [NN*FOUT];
__device__ float g_ua [NN*FOUT];
__device__ float g_dh [NN*128];
__device__ float g_part[KSPLIT*NN*FOUT];
__device__ float g_WT [FOUT*FOUT];
__device__ int   g_adj_idx[NN*MAXNNZ];
__device__ int   g_adj_cnt[NN];
__device__ int   g_gn_idx [NN*MAXNNZ];
__device__ int   g_gn_cnt [NN];

// ---------------- build sparse row lists (deterministic order) ----------------
__global__ void build_list_kernel(const float* __restrict__ mat, int* __restrict__ idx,
                                  int* __restrict__ cnt) {
    int row = blockIdx.x;
    int tid = threadIdx.x;
    const float* r = mat + (size_t)row * NN;
    __shared__ int counts[256];
    __shared__ int offs[256];
    int base = tid * 16;
    int c = 0;
    #pragma unroll
    for (int j = 0; j < 16; j++) c += (r[base + j] != 0.0f);
    counts[tid] = c;
    __syncthreads();
    if (tid == 0) {
        int acc = 0;
        for (int i = 0; i < 256; i++) { offs[i] = acc; acc += counts[i]; }
        cnt[row] = acc;
    }
    __syncthreads();
    int o = offs[tid];
    int* dst = idx + (size_t)row * MAXNNZ;
    #pragma unroll
    for (int j = 0; j < 16; j++) {
        if (r[base + j] != 0.0f) dst[o++] = base + j;
    }
}

// ---------------- tf32 WMMA GEMM: C = A[M,K] @ B[K,N] (row-major) -------------
// block: 256 threads = 8 warps. Tile BM=128, BN=64. Each warp: 16 rows x 64 cols.
// split-K via blockIdx.z (partials written to C + bz*partStride).
__global__ void gemm_tf32_kernel(const float* __restrict__ A, const float* __restrict__ B,
                                 float* __restrict__ C,
                                 int M, int N, int K, int kChunk, long long partStride) {
    int bz = blockIdx.z;
    int k0 = bz * kChunk;
    int k1 = min(K, k0 + kChunk);
    float* Cp = C + (long long)bz * partStride;
    int row0 = blockIdx.y * 128;
    int col0 = blockIdx.x * 64;
    int tid = threadIdx.x;
    int wid = tid >> 5;
    int lane = tid & 31;

    __shared__ float As[128][32];
    __shared__ float Bs[32][72];     // ldm 72 (multiple of 8), reduces conflicts
    __shared__ float Cb[8][256];     // per-warp bounce buffer for ragged N edge

    wmma::fragment<wmma::accumulator, 16, 16, 8, float> acc[4];
    #pragma unroll
    for (int f = 0; f < 4; f++) wmma::fill_fragment(acc[f], 0.0f);

    for (int kk = k0; kk < k1; kk += 32) {
        #pragma unroll
        for (int t = tid; t < 4096; t += 256) {
            int m = t >> 5, k = t & 31;
            int gk = kk + k;
            As[m][k] = (gk < k1) ? A[(size_t)(row0 + m) * K + gk] : 0.0f;
        }
        #pragma unroll
        for (int t = tid; t < 2048; t += 256) {
            int k = t >> 6, n = t & 63;
            int gk = kk + k, gn = col0 + n;
            Bs[k][n] = (gk < k1 && gn < N) ? B[(size_t)gk * N + gn] : 0.0f;
        }
        __syncthreads();
        #pragma unroll
        for (int ks = 0; ks < 32; ks += 8) {
            wmma::fragment<wmma::matrix_a, 16, 16, 8, wmma::precision::tf32, wmma::row_major> af;
            wmma::load_matrix_sync(af, &As[wid * 16][ks], 32);
            #pragma unroll
            for (int i = 0; i < af.num_elements; i++) af.x[i] = wmma::__float_to_tf32(af.x[i]);
            #pragma unroll
            for (int f = 0; f < 4; f++) {
                wmma::fragment<wmma::matrix_b, 16, 16, 8, wmma::precision::tf32, wmma::row_major> bf;
                wmma::load_matrix_sync(bf, &Bs[ks][f * 16], 72);
                #pragma unroll
                for (int i = 0; i < bf.num_elements; i++) bf.x[i] = wmma::__float_to_tf32(bf.x[i]);
                wmma::mma_sync(acc[f], af, bf, acc[f]);
            }
        }
        __syncthreads();
    }

    int r0 = row0 + wid * 16;
    #pragma unroll
    for (int f = 0; f < 4; f++) {
        int c0 = col0 + f * 16;
        if (c0 + 16 <= N) {
            wmma::store_matrix_sync(&Cp[(size_t)r0 * N + c0], acc[f], N, wmma::mem_row_major);
        } else if (c0 < N) {
            wmma::store_matrix_sync(&Cb[wid][0], acc[f], 16, wmma::mem_row_major);
            __syncwarp();
            int valid = N - c0;
            for (int e = lane; e < 256; e += 32) {
                int rr = e >> 4, cc = e & 15;
                if (cc < valid) Cp[(size_t)(r0 + rr) * N + c0 + cc] = Cb[wid][e];
            }
        }
    }
}

__global__ void reduce_part_kernel(const float* __restrict__ part, float* __restrict__ out,
                                   int mn, int parts) {
    int i = blockIdx.x * blockDim.x + threadIdx.x;
    if (i < mn) {
        float s = 0.0f;
        for (int z = 0; z < parts; z++) s += part[(size_t)z * mn + i];
        out[i] = s;
    }
}

// ---------------- generic tiled fp32 GEMM (small ops): C = act(A@B + bias) ----
__global__ void gemm_kernel(const float* __restrict__ A, const float* __restrict__ B,
                            const float* __restrict__ bias, float* __restrict__ C,
                            int M, int N, int K, int act) {
    int row0 = blockIdx.y * 64;
    int col0 = blockIdx.x * 64;
    int tid = threadIdx.x;
    int tx = tid & 15, ty = tid >> 4;

    __shared__ float As[16][64];
    __shared__ float Bs[16][65];

    float acc[4][4];
    #pragma unroll
    for (int i = 0; i < 4; i++)
        #pragma unroll
        for (int j = 0; j < 4; j++) acc[i][j] = 0.0f;

    for (int kk = 0; kk < K; kk += 16) {
        #pragma unroll
        for (int t = tid; t < 1024; t += 256) {
            int m = t >> 4, k = t & 15;
            int gk = kk + k;
            As[k][m] = (gk < K) ? A[(size_t)(row0 + m) * K + gk] : 0.0f;
        }
        #pragma unroll
        for (int t = tid; t < 1024; t += 256) {
            int k = t >> 6, n = t & 63;
            int gk = kk + k, gn = col0 + n;
            Bs[k][n] = (gk < K && gn < N) ? B[(size_t)gk * N + gn] : 0.0f;
        }
        __syncthreads();
        #pragma unroll
        for (int k = 0; k < 16; k++) {
            float a0 = As[k][ty * 4 + 0], a1 = As[k][ty * 4 + 1];
            float a2 = As[k][ty * 4 + 2], a3 = As[k][ty * 4 + 3];
            float b0 = Bs[k][tx * 4 + 0], b1 = Bs[k][tx * 4 + 1];
            float b2 = Bs[k][tx * 4 + 2], b3 = Bs[k][tx * 4 + 3];
            acc[0][0] += a0 * b0; acc[0][1] += a0 * b1; acc[0][2] += a0 * b2; acc[0][3] += a0 * b3;
            acc[1][0] += a1 * b0; acc[1][1] += a1 * b1; acc[1][2] += a1 * b2; acc[1][3] += a1 * b3;
            acc[2][0] += a2 * b0; acc[2][1] += a2 * b1; acc[2][2] += a2 * b2; acc[2][3] += a2 * b3;
            acc[3][0] += a3 * b0; acc[3][1] += a3 * b1; acc[3][2] += a3 * b2; acc[3][3] += a3 * b3;
        }
        __syncthreads();
    }
    #pragma unroll
    for (int i = 0; i < 4; i++) {
        int r = row0 + ty * 4 + i;
        #pragma unroll
        for (int j = 0; j < 4; j++) {
            int c = col0 + tx * 4 + j;
            if (c < N) {
                float v = acc[i][j];
                if (bias) v += bias[c];
                if (act) v = fmaxf(v, 0.0f);
                C[(size_t)r * N + c] = v;
            }
        }
    }
}

// ---------------- s = Wh@a_src, d = Wh@a_dst (warp per row) ----------------
__global__ void sd_kernel(const float* __restrict__ Wh, const float* __restrict__ a_src,
                          const float* __restrict__ a_dst, float* __restrict__ s,
                          float* __restrict__ d) {
    int row = blockIdx.x * 8 + (threadIdx.x >> 5);
    int lane = threadIdx.x & 31;
    if (row < NN) {
        const float* w = Wh + (size_t)row * 64;
        float vs = w[lane] * a_src[lane] + w[lane + 32] * a_src[lane + 32];
        float vd = w[lane] * a_dst[lane] + w[lane + 32] * a_dst[lane + 32];
        #pragma unroll
        for (int o = 16; o > 0; o >>= 1) {
            vs += __shfl_down_sync(0xffffffffu, vs, o);
            vd += __shfl_down_sync(0xffffffffu, vd, o);
        }
        if (lane == 0) { s[row] = vs; d[row] = vd; }
    }
}

// ---------------- sparse masked softmax + spmm with Wh ----------------
__global__ void att_kernel(const int* __restrict__ idx, const int* __restrict__ cnt,
                           const float* __restrict__ s, const float* __restrict__ d,
                           const float* __restrict__ Wh, float* __restrict__ out) {
    int row = blockIdx.x, tid = threadIdx.x;
    int n = cnt[row];
    const int* lst = idx + (size_t)row * MAXNNZ;
    __shared__ float e[MAXNNZ];
    __shared__ float red[256];
    __shared__ float accsh[4][64];
    float si = s[row];
    float mx = -3.4e38f;
    for (int t = tid; t < n; t += 256) {
        int j = lst[t];
        float v = si + d[j];
        v = v > 0.0f ? v : 0.2f * v;   // LeakyReLU(0.2)
        e[t] = v;
        mx = fmaxf(mx, v);
    }
    red[tid] = mx;
    __syncthreads();
    for (int st = 128; st > 0; st >>= 1) {
        if (tid < st) red[tid] = fmaxf(red[tid], red[tid + st]);
        __syncthreads();
    }
    mx = red[0];
    __syncthreads();
    float sm = 0.0f;
    for (int t = tid; t < n; t += 256) {
        float w = expf(e[t] - mx);
        e[t] = w;
        sm += w;
    }
    red[tid] = sm;
    __syncthreads();
    for (int st = 128; st > 0; st >>= 1) {
        if (tid < st) red[tid] += red[tid + st];
        __syncthreads();
    }
    float inv = 1.0f / red[0];
    int grp = tid >> 6, lane = tid & 63;
    float acc = 0.0f;
    for (int t = grp; t < n; t += 4) acc += e[t] * Wh[(size_t)lst[t] * 64 + lane];
    accsh[grp][lane] = acc;
    __syncthreads();
    if (grp == 0)
        out[(size_t)row * 64 + lane] =
            (accsh[0][lane] + accsh[1][lane] + accsh[2][lane] + accsh[3][lane]) * inv;
}

// ---------------- adjz = adj @ z  (binary adj, list-based sum) ----------------
__global__ void agg_kernel(const int* __restrict__ idx, const int* __restrict__ cnt,
                           const float* __restrict__ z, float* __restrict__ out) {
    int row = blockIdx.x * 4 + (threadIdx.x >> 6);
    int lane = threadIdx.x & 63;
    int n = cnt[row];
    const int* lst = idx + (size_t)row * MAXNNZ;
    float a = 0.0f;
    for (int t = 0; t < n; t++) a += z[(size_t)lst[t] * 64 + lane];
    out[(size_t)row * 64 + lane] = a;
}

// ---------------- readout: mean over gn-list, L2 normalize, sigmoid ----------------
__global__ void readout_kernel(const int* __restrict__ idx, const int* __restrict__ cnt,
                               const float* __restrict__ emb, float* __restrict__ g) {
    int row = blockIdx.x, tid = threadIdx.x;
    int n = cnt[row];
    const int* lst = idx + (size_t)row * MAXNNZ;
    __shared__ float accsh[4][64];
    __shared__ float v[64];
    __shared__ float red[64];
    int grp = tid >> 6, lane = tid & 63;
    float a = 0.0f;
    for (int t = grp; t < n; t += 4) a += emb[(size_t)lst[t] * 64 + lane];
    accsh[grp][lane] = a;
    __syncthreads();
    if (grp == 0)
        v[lane] = (accsh[0][lane] + accsh[1][lane] + accsh[2][lane] + accsh[3][lane]) / (float)n;
    __syncthreads();
    if (tid < 64) red[tid] = v[tid] * v[tid];
    __syncthreads();
    for (int st = 32; st > 0; st >>= 1) {
        if (tid < st) red[tid] += red[tid + st];
        __syncthreads();
    }
    float den = fmaxf(sqrtf(red[0]), 1e-12f);
    if (tid < 64) {
        float x = v[tid] / den;
        g[(size_t)row * 64 + tid] = 1.0f / (1.0f + expf(-x));
    }
}

// ---------------- elementwise ----------------
__global__ void relu_kernel(const float* __restrict__ in, float* __restrict__ out, int n) {
    int i = blockIdx.x * blockDim.x + threadIdx.x;
    if (i < n) out[i] = fmaxf(in[i], 0.0f);
}
__global__ void copy_kernel(const float* __restrict__ in, float* __restrict__ out, int n) {
    int i = blockIdx.x * blockDim.x + threadIdx.x;
    if (i < n) out[i] = in[i];
}
__global__ void transpose64_kernel(const float* __restrict__ W, float* __restrict__ WT) {
    for (int t = threadIdx.x; t < 64 * 64; t += blockDim.x) {
        int i = t >> 6, j = t & 63;
        WT[j * 64 + i] = W[t];
    }
}

// ---------------- bilinear outputs ----------------
__global__ void bilin_kernel(const float* __restrict__ x0, const float* __restrict__ x1,
                             const float* __restrict__ u, const float* __restrict__ b,
                             float* __restrict__ out) {
    int row = blockIdx.x * 8 + (threadIdx.x >> 5);
    int lane = threadIdx.x & 31;
    if (row < NN) {
        const float* ur = u + (size_t)row * 64;
        const float* r0 = x0 + (size_t)row * 64;
        const float* r1 = x1 + (size_t)row * 64;
        float v0 = r0[lane] * ur[lane] + r0[lane + 32] * ur[lane + 32];
        float v1 = r1[lane] * ur[lane] + r1[lane + 32] * ur[lane + 32];
        #pragma unroll
        for (int o = 16; o > 0; o >>= 1) {
            v0 += __shfl_down_sync(0xffffffffu, v0, o);
            v1 += __shfl_down_sync(0xffffffffu, v1, o);
        }
        if (lane == 0) {
            out[(size_t)row * 2 + 0] = v0 + b[0];
            out[(size_t)row * 2 + 1] = v1 + b[0];
        }
    }
}

// ---------------- host ----------------
static void* sym(const void* s) {
    void* p = nullptr;
    cudaGetSymbolAddress(&p, s);
    return p;
}

extern "C" void kernel_launch(void* const* d_in, const int* in_sizes, int n_in,
                              void* d_out, int out_size) {
    const float* feat   = (const float*)d_in[0];
    const float* feat_a = (const float*)d_in[1];
    const float* adj    = (const float*)d_in[2];
    const float* gn     = (const float*)d_in[3];
    const float* w1     = (const float*)d_in[4];
    const float* w2     = (const float*)d_in[5];
    const float* attW   = (const float*)d_in[6];
    const float* a_src  = (const float*)d_in[7];
    const float* a_dst  = (const float*)d_in[8];
    const float* mW1 = (const float*)d_in[9];  const float* mb1 = (const float*)d_in[10];
    const float* mW2 = (const float*)d_in[11]; const float* mb2 = (const float*)d_in[12];
    const float* mW3 = (const float*)d_in[13]; const float* mb3 = (const float*)d_in[14];
    const float* dW1 = (const float*)d_in[15]; const float* db1 = (const float*)d_in[16];
    const float* dW2 = (const float*)d_in[17]; const float* db2 = (const float*)d_in[18];
    const float* bilW = (const float*)d_in[19];
    const float* bilb = (const float*)d_in[20];

    float* out      = (float*)d_out;
    float* out_h    = out + (size_t)NN * FOUT;
    float* out_ret  = out_h + (size_t)NN * FIN;
    float* out_reta = out_ret + (size_t)NN * 2;

    float* X1  = (float*)sym(g_X1);   float* X1a = (float*)sym(g_X1a);
    float* Wh  = (float*)sym(g_Wh);
    float* sv  = (float*)sym(g_s);    float* dv  = (float*)sym(g_d);
    float* att = (float*)sym(g_att);
    float* t1  = (float*)sym(g_t1);   float* t2  = (float*)sym(g_t2);
    float* z   = (float*)sym(g_z);    float* za  = (float*)sym(g_za);
    float* adjz = (float*)sym(g_adjz);
    float* emb = (float*)sym(g_emb);  float* emba = (float*)sym(g_emba);
    float* gv  = (float*)sym(g_g);    float* gva  = (float*)sym(g_ga);
    float* dc  = (float*)sym(g_dc);   float* dca  = (float*)sym(g_dca);
    float* dpl = (float*)sym(g_dpl);  float* dmi  = (float*)sym(g_dmi);
    float* u   = (float*)sym(g_u);    float* ua   = (float*)sym(g_ua);
    float* dh  = (float*)sym(g_dh);
    float* part = (float*)sym(g_part);
    float* WT  = (float*)sym(g_WT);
    int* aidx = (int*)sym(g_adj_idx); int* acnt = (int*)sym(g_adj_cnt);
    int* gidx = (int*)sym(g_gn_idx);  int* gcnt = (int*)sym(g_gn_cnt);

    // 1. sparse lists (adj read once, gn read once)
    build_list_kernel<<<NN, 256>>>(adj, aidx, acnt);
    build_list_kernel<<<NN, 256>>>(gn, gidx, gcnt);

    // 2. X1 = feat @ w1, X1a = feat_a @ w1   (tf32 tensor cores, split-K=8)
    {
        dim3 grid(1, NN / 128, KSPLIT);
        long long ps = (long long)NN * FOUT;
        int kChunk = (FIN + KSPLIT - 1) / KSPLIT;  // 375
        gemm_tf32_kernel<<<grid, 256>>>(feat, w1, part, NN, FOUT, FIN, kChunk, ps);
        reduce_part_kernel<<<(NN * FOUT + 255) / 256, 256>>>(part, X1, NN * FOUT, KSPLIT);
        gemm_tf32_kernel<<<grid, 256>>>(feat_a, w1, part, NN, FOUT, FIN, kChunk, ps);
        reduce_part_kernel<<<(NN * FOUT + 255) / 256, 256>>>(part, X1a, NN * FOUT, KSPLIT);
    }

    // 3. two GAT+MLP paths
    for (int p = 0; p < 2; p++) {
        const float* X = p == 0 ? X1 : X1a;
        float* zz = p == 0 ? z : za;
        gemm_kernel<<<dim3(1, NN / 64, 1), 256>>>(X, attW, nullptr, Wh, NN, 64, 64, 0);
        sd_kernel<<<NN / 8, 256>>>(Wh, a_src, a_dst, sv, dv);
        att_kernel<<<NN, 256>>>(aidx, acnt, sv, dv, Wh, att);
        gemm_kernel<<<dim3(4, NN / 64, 1), 256>>>(att, mW1, mb1, t1, NN, 256, 64, 1);
        gemm_kernel<<<dim3(2, NN / 64, 1), 256>>>(t1, mW2, mb2, t2, NN, 128, 256, 1);
        gemm_kernel<<<dim3(1, NN / 64, 1), 256>>>(t2, mW3, mb3, zz, NN, 64, 128, 0);
    }

    // 4. hiden_emb = z
    copy_kernel<<<(NN * FOUT + 255) / 256, 256>>>(z, out, NN * FOUT);

    // 5. h = (adj @ z) @ w2   (reassociated; adj binary so agg = neighbor sum)
    agg_kernel<<<NN / 4, 256>>>(aidx, acnt, z, adjz);
    gemm_tf32_kernel<<<dim3((FIN + 63) / 64, NN / 128, 1), 256>>>(
        adjz, w2, out_h, NN, FIN, FOUT, FOUT, 0);

    // 6. emb / emb_a, readouts
    relu_kernel<<<(NN * FOUT + 255) / 256, 256>>>(z, emb, NN * FOUT);
    relu_kernel<<<(NN * FOUT + 255) / 256, 256>>>(za, emba, NN * FOUT);
    readout_kernel<<<NN, 256>>>(gidx, gcnt, emb, gv);
    readout_kernel<<<NN, 256>>>(gidx, gcnt, emba, gva);

    // 7. discriminator MLPs
    const float* dins[4] = { gv, gva, emb, emba };
    float* douts[4] = { dc, dca, dpl, dmi };
    for (int i = 0; i < 4; i++) {
        gemm_kernel<<<dim3(2, NN / 64, 1), 256>>>(dins[i], dW1, db1, dh, NN, 128, 64, 1);
        gemm_kernel<<<dim3(1, NN / 64, 1), 256>>>(dh, dW2, db2, douts[i], NN, 64, 128, 0);
    }

    // 8. bilinear: u = dc @ bilW^T ; ret[:,0]=dot(dpl,u)+b, ret[:,1]=dot(dmi,u)+b
    transpose64_kernel<<<1, 256>>>(bilW, WT);
    gemm_kernel<<<dim3(1, NN / 64, 1), 256>>>(dc, WT, nullptr, u, NN, 64, 64, 0);
    gemm_kernel<<<dim3(1, NN / 64, 1), 256>>>(dca, WT, nullptr, ua, NN, 64, 64, 0);
    bilin_kernel<<<NN / 8, 256>>>(dpl, dmi, u, bilb, out_ret);
    bilin_kernel<<<NN / 8, 256>>>(dmi, dpl, ua, bilb, out_reta);
}